// round 6
// baseline (speedup 1.0000x reference)
#include <cuda_runtime.h>
#include <cuda_bf16.h>
#include <math.h>

#define N_NODES 50000
#define N_EDGES 800000
#define E_TOT   (N_EDGES + N_NODES)   // edges + self loops = 850000
#define F       128                   // in/out feature dim
#define HEADS   4
#define HDIM    32
#define NEG_SLOPE 0.2f

// ----------------------------------------------------------------------------
// Scratch (device globals; no allocation allowed)
// ----------------------------------------------------------------------------
__device__ float g_x0[N_NODES * F];      // layer ping buffer
__device__ float g_x1[N_NODES * F];      // layer pong buffer
__device__ uint2 g_h2[N_NODES * 32];     // h in bf16: 128 bf16 = 32 uint2 per row
__device__ float g_as[N_NODES * HEADS];  // alpha_src per node (fp32)
__device__ float g_ad[N_NODES * HEADS];  // alpha_dst per node (fp32)
__device__ int   g_deg[N_NODES];
__device__ int   g_off[N_NODES + 1];
__device__ int   g_cur[N_NODES];
__device__ int   g_csr[E_TOT];           // src node per CSR slot (grouped by dst)

// ----------------------------------------------------------------------------
// Packed fp32x2 helpers (Blackwell: FFMA2 only reachable via PTX fma.rn.f32x2)
// ----------------------------------------------------------------------------
__device__ __forceinline__ unsigned long long pack2(float lo, float hi) {
    unsigned long long r;
    asm("mov.b64 %0, {%1, %2};" : "=l"(r) : "f"(lo), "f"(hi));
    return r;
}
__device__ __forceinline__ void unpack2(unsigned long long v, float& lo, float& hi) {
    asm("mov.b64 {%0, %1}, %2;" : "=f"(lo), "=f"(hi) : "l"(v));
}
#define FMA2(d, a, b) asm("fma.rn.f32x2 %0, %1, %2, %0;" : "+l"(d) : "l"(a), "l"(b))

// ----------------------------------------------------------------------------
// CSR construction (edge_index is int32)
// ----------------------------------------------------------------------------
__global__ void zero_deg_kernel(int* deg) {
    int i = blockIdx.x * blockDim.x + threadIdx.x;
    if (i < N_NODES) deg[i] = 0;
}

__global__ void hist_kernel(const int* __restrict__ ei, int* __restrict__ deg) {
    int i = blockIdx.x * blockDim.x + threadIdx.x;
    if (i >= E_TOT) return;
    int dst = (i < N_EDGES) ? ei[N_EDGES + i] : (i - N_EDGES);
    if (dst >= 0 && dst < N_NODES) atomicAdd(&deg[dst], 1);
}

// single-block exclusive scan over 50000 degrees
__global__ void scan_kernel(const int* __restrict__ deg, int* __restrict__ off,
                            int* __restrict__ cur) {
    __shared__ int part[1024];
    const int CH = (N_NODES + 1023) / 1024;  // 49
    int t = threadIdx.x;
    int b = t * CH;
    int e = min(b + CH, N_NODES);
    int s = 0;
    for (int i = b; i < e; i++) s += deg[i];
    part[t] = s;
    __syncthreads();
    for (int o = 1; o < 1024; o <<= 1) {
        int v = (t >= o) ? part[t - o] : 0;
        __syncthreads();
        part[t] += v;
        __syncthreads();
    }
    int run = (t == 0) ? 0 : part[t - 1];
    for (int i = b; i < e; i++) {
        off[i] = run;
        cur[i] = run;
        run += deg[i];
    }
    if (t == 0) off[N_NODES] = part[1023];
}

__global__ void fill_kernel(const int* __restrict__ ei, int* __restrict__ cur,
                            int* __restrict__ csr) {
    int i = blockIdx.x * blockDim.x + threadIdx.x;
    if (i >= E_TOT) return;
    int src, dst;
    if (i < N_EDGES) { src = ei[i]; dst = ei[N_EDGES + i]; }
    else             { src = i - N_EDGES; dst = src; }
    if (dst < 0 || dst >= N_NODES) return;
    if (src < 0) src = 0; if (src >= N_NODES) src = N_NODES - 1;
    int pos = atomicAdd(&cur[dst], 1);
    csr[pos] = src;
}

// ----------------------------------------------------------------------------
// GEMM + alpha fusion: h[N,128] = x[N,128] @ W[128,128] (fp32 accum),
// alphas from fp32 registers; h stored as bf16 (halves gather traffic).
// 64-row tile, 256 threads. Inner product uses packed fma.rn.f32x2.
// ----------------------------------------------------------------------------
__global__ __launch_bounds__(256) void gemm_alpha_kernel(
    const float* __restrict__ x, const float* __restrict__ W,
    const float* __restrict__ a_s, const float* __restrict__ a_d,
    uint2* __restrict__ h2, float* __restrict__ out_s, float* __restrict__ out_d) {
    __shared__ float xs[64 * F];
    int t = threadIdx.x;
    int row0 = blockIdx.x * 64;

    const float4* x4 = reinterpret_cast<const float4*>(x);
    float4* xs4 = reinterpret_cast<float4*>(xs);
#pragma unroll
    for (int i = 0; i < 8; i++) {
        int idx = t + i * 256;          // 0..2047 float4 slots
        int r = idx >> 5;
        int cc = idx & 31;
        float4 v = make_float4(0.f, 0.f, 0.f, 0.f);
        if (row0 + r < N_NODES) v = x4[(size_t)(row0 + r) * 32 + cc];
        xs4[idx] = v;
    }
    __syncthreads();

    int t_row = t >> 5, t_col = t & 31;

    unsigned long long acc2[4][4];  // [row-pair][col j]
#pragma unroll
    for (int rr = 0; rr < 4; rr++)
#pragma unroll
        for (int j = 0; j < 4; j++) acc2[rr][j] = pack2(0.f, 0.f);

    const float4* W4 = reinterpret_cast<const float4*>(W);
    const float* xbase = xs + t_row * 8 * F;
#pragma unroll 4
    for (int k = 0; k < F; k++) {
        float4 w = W4[k * 32 + t_col];
        unsigned long long w0 = pack2(w.x, w.x);
        unsigned long long w1 = pack2(w.y, w.y);
        unsigned long long w2 = pack2(w.z, w.z);
        unsigned long long w3 = pack2(w.w, w.w);
#pragma unroll
        for (int rr = 0; rr < 4; rr++) {
            float xa = xbase[(2 * rr) * F + k];
            float xb = xbase[(2 * rr + 1) * F + k];
            unsigned long long xp = pack2(xa, xb);
            FMA2(acc2[rr][0], xp, w0);
            FMA2(acc2[rr][1], xp, w1);
            FMA2(acc2[rr][2], xp, w2);
            FMA2(acc2[rr][3], xp, w3);
        }
    }

    float accf[8][4];
#pragma unroll
    for (int rr = 0; rr < 4; rr++)
#pragma unroll
        for (int j = 0; j < 4; j++)
            unpack2(acc2[rr][j], accf[2 * rr][j], accf[2 * rr + 1][j]);

    // store h as bf16 (4 channels -> 2 bf16x2 -> uint2)
#pragma unroll
    for (int r = 0; r < 8; r++) {
        int row = row0 + t_row * 8 + r;
        if (row < N_NODES) {
            __nv_bfloat162 p0 = __floats2bfloat162_rn(accf[r][0], accf[r][1]);
            __nv_bfloat162 p1 = __floats2bfloat162_rn(accf[r][2], accf[r][3]);
            uint2 v;
            v.x = *reinterpret_cast<unsigned int*>(&p0);
            v.y = *reinterpret_cast<unsigned int*>(&p1);
            h2[(size_t)row * 32 + t_col] = v;
        }
    }

    // fused alpha (fp32): channels of head hd live in lanes t_col = 8*hd..8*hd+7
    float4 asv = reinterpret_cast<const float4*>(a_s)[t_col];
    float4 adv = reinterpret_cast<const float4*>(a_d)[t_col];
    int head = t_col >> 3;
#pragma unroll
    for (int r = 0; r < 8; r++) {
        int row = row0 + t_row * 8 + r;
        float ps = accf[r][0] * asv.x + accf[r][1] * asv.y +
                   accf[r][2] * asv.z + accf[r][3] * asv.w;
        float pd = accf[r][0] * adv.x + accf[r][1] * adv.y +
                   accf[r][2] * adv.z + accf[r][3] * adv.w;
#pragma unroll
        for (int o = 1; o < 8; o <<= 1) {
            ps += __shfl_xor_sync(0xffffffffu, ps, o);
            pd += __shfl_xor_sync(0xffffffffu, pd, o);
        }
        if ((t_col & 7) == 0 && row < N_NODES) {
            out_s[row * HEADS + head] = ps;
            out_d[row * HEADS + head] = pd;
        }
    }
}

// ----------------------------------------------------------------------------
// Fused softmax + aggregation: one warp per dst node; h gathered in bf16.
// lane covers channels 4*lane..4*lane+3; head = lane>>3.
// q identical across the 8 lanes of a head -> den needs no reduction.
// ----------------------------------------------------------------------------
__global__ __launch_bounds__(256) void agg_fused_kernel(
    const uint2* __restrict__ h2, const int* __restrict__ off,
    const int* __restrict__ csr, const float* __restrict__ as,
    const float* __restrict__ ad, const float* __restrict__ bias,
    float* __restrict__ out) {
    int warp = threadIdx.x >> 5;
    int lane = threadIdx.x & 31;
    int n = blockIdx.x * 8 + warp;
    if (n >= N_NODES) return;

    int head = lane >> 3;
    float ad_h = ad[n * HEADS + head];

    float4 acc = make_float4(0.f, 0.f, 0.f, 0.f);
    float den = 0.f;
    int s0 = off[n], s1 = off[n + 1];

    int pos = s0;
    for (; pos + 4 <= s1; pos += 4) {
        int sa = csr[pos];
        int sb = csr[pos + 1];
        int sc = csr[pos + 2];
        int sd = csr[pos + 3];
        float ea = as[sa * HEADS + head] + ad_h;
        float eb = as[sb * HEADS + head] + ad_h;
        float ec = as[sc * HEADS + head] + ad_h;
        float ed = as[sd * HEADS + head] + ad_h;
        ea = ea > 0.f ? ea : NEG_SLOPE * ea;
        eb = eb > 0.f ? eb : NEG_SLOPE * eb;
        ec = ec > 0.f ? ec : NEG_SLOPE * ec;
        ed = ed > 0.f ? ed : NEG_SLOPE * ed;
        float qa = __expf(ea), qb = __expf(eb), qc = __expf(ec), qd = __expf(ed);
        uint2 va = h2[(size_t)sa * 32 + lane];
        uint2 vb = h2[(size_t)sb * 32 + lane];
        uint2 vc = h2[(size_t)sc * 32 + lane];
        uint2 vd = h2[(size_t)sd * 32 + lane];
        float2 a0 = __bfloat1622float2(*reinterpret_cast<__nv_bfloat162*>(&va.x));
        float2 a1 = __bfloat1622float2(*reinterpret_cast<__nv_bfloat162*>(&va.y));
        float2 b0 = __bfloat1622float2(*reinterpret_cast<__nv_bfloat162*>(&vb.x));
        float2 b1 = __bfloat1622float2(*reinterpret_cast<__nv_bfloat162*>(&vb.y));
        float2 c0 = __bfloat1622float2(*reinterpret_cast<__nv_bfloat162*>(&vc.x));
        float2 c1 = __bfloat1622float2(*reinterpret_cast<__nv_bfloat162*>(&vc.y));
        float2 d0 = __bfloat1622float2(*reinterpret_cast<__nv_bfloat162*>(&vd.x));
        float2 d1 = __bfloat1622float2(*reinterpret_cast<__nv_bfloat162*>(&vd.y));
        acc.x += qa * a0.x + qb * b0.x + qc * c0.x + qd * d0.x;
        acc.y += qa * a0.y + qb * b0.y + qc * c0.y + qd * d0.y;
        acc.z += qa * a1.x + qb * b1.x + qc * c1.x + qd * d1.x;
        acc.w += qa * a1.y + qb * b1.y + qc * c1.y + qd * d1.y;
        den += (qa + qb) + (qc + qd);
    }
    for (; pos < s1; pos++) {
        int sa = csr[pos];
        float e = as[sa * HEADS + head] + ad_h;
        e = e > 0.f ? e : NEG_SLOPE * e;
        float q = __expf(e);
        uint2 va = h2[(size_t)sa * 32 + lane];
        float2 a0 = __bfloat1622float2(*reinterpret_cast<__nv_bfloat162*>(&va.x));
        float2 a1 = __bfloat1622float2(*reinterpret_cast<__nv_bfloat162*>(&va.y));
        acc.x += q * a0.x; acc.y += q * a0.y;
        acc.z += q * a1.x; acc.w += q * a1.y;
        den += q;
    }

    float inv = 1.f / den;   // deg >= 1 (self loop), den > 0
    float4 bv = reinterpret_cast<const float4*>(bias)[lane];
    float4 o;
    o.x = fmaxf(acc.x * inv + bv.x, 0.f);
    o.y = fmaxf(acc.y * inv + bv.y, 0.f);
    o.z = fmaxf(acc.z * inv + bv.z, 0.f);
    o.w = fmaxf(acc.w * inv + bv.w, 0.f);
    reinterpret_cast<float4*>(out)[(size_t)n * 32 + lane] = o;
}

// ----------------------------------------------------------------------------
// Launch
// ----------------------------------------------------------------------------
extern "C" void kernel_launch(void* const* d_in, const int* in_sizes, int n_in,
                              void* d_out, int out_size) {
    const float* x    = (const float*)d_in[0];
    const int*   ei   = (const int*)d_in[1];
    const float* Ws   = (const float*)d_in[2];
    const float* a_s  = (const float*)d_in[3];
    const float* a_d  = (const float*)d_in[4];
    const float* bias = (const float*)d_in[5];
    float*       out  = (float*)d_out;

    void* pv;
    cudaGetSymbolAddress(&pv, g_x0);  float* x0  = (float*)pv;
    cudaGetSymbolAddress(&pv, g_x1);  float* x1  = (float*)pv;
    cudaGetSymbolAddress(&pv, g_h2);  uint2* h2  = (uint2*)pv;
    cudaGetSymbolAddress(&pv, g_as);  float* as  = (float*)pv;
    cudaGetSymbolAddress(&pv, g_ad);  float* ad  = (float*)pv;
    cudaGetSymbolAddress(&pv, g_deg); int*   deg = (int*)pv;
    cudaGetSymbolAddress(&pv, g_off); int*   off = (int*)pv;
    cudaGetSymbolAddress(&pv, g_cur); int*   cur = (int*)pv;
    cudaGetSymbolAddress(&pv, g_csr); int*   csr = (int*)pv;

    // CSR build (once; reused by all 3 layers)
    zero_deg_kernel<<<(N_NODES + 255) / 256, 256>>>(deg);
    hist_kernel<<<(E_TOT + 255) / 256, 256>>>(ei, deg);
    scan_kernel<<<1, 1024>>>(deg, off, cur);
    fill_kernel<<<(E_TOT + 255) / 256, 256>>>(ei, cur, csr);

    for (int l = 0; l < 3; l++) {
        const float* xin = (l == 0) ? x : ((l == 1) ? x0 : x1);
        float* xout = (l == 0) ? x0 : ((l == 1) ? x1 : out);
        gemm_alpha_kernel<<<(N_NODES + 63) / 64, 256>>>(
            xin, Ws + (size_t)l * F * F, a_s + l * F, a_d + l * F, h2, as, ad);
        agg_fused_kernel<<<(N_NODES + 7) / 8, 256>>>(
            h2, off, csr, as, ad, bias + l * F, xout);
    }
}